// round 5
// baseline (speedup 1.0000x reference)
#include <cuda_runtime.h>

// Fixed shapes
#define N_TOK 4096          // B*S
#define DIM   1024
#define NE    8
#define CAP   1280
#define NEC   ((size_t)N_TOK * NE * CAP)   // 41,943,040 floats
#define ECD   ((size_t)NE * CAP * DIM)     // 10,485,760 floats

#define LB    512                      // logits blocks (8 tokens each, warp/token)
#define ZB    4096                     // zero-fill blocks
#define TB    512                      // tail batch blocks
#define GRID  (LB + ZB + TB + 1)       // +1 patch block

#define ZF4      (2 * NEC / 4)         // float4s to zero (w+m) = 20,971,520
#define ZF4_PER  (ZF4 / ZB)            // 5120 per block = 20 iters x 256 thr

// Scratch (no allocs allowed -> device globals)
__device__ int      g_top[2][N_TOK];
__device__ float    g_prob[2][N_TOK];
__device__ int      g_slot_token[NE * CAP];
__device__ unsigned g_tok_off[2][N_TOK];   // e*CAP+r within token's [E,cap] row, 0xFFFFFFFF invalid
__device__ float    g_tok_val[2][N_TOK];
__device__ int      g_done;       // logits blocks finished
__device__ int      g_flag;       // scan finished
__device__ int      g_zero_done;  // zero blocks finished

__global__ void k_init() { g_done = 0; g_flag = 0; g_zero_done = 0; }

__global__ void __launch_bounds__(256) k_fused(
    const float* __restrict__ x,
    const float* __restrict__ w,
    float* __restrict__ out,      // base: w region, then m, (batches/logits via offsets)
    float* __restrict__ out_b,
    float* __restrict__ out_l) {

    const int tid = threadIdx.x;

    // ================= zero-fill blocks (never wait) =================
    if (blockIdx.x >= LB && blockIdx.x < LB + ZB) {
        const int zid = blockIdx.x - LB;
        float4* dst = (float4*)out + (size_t)zid * ZF4_PER;
        const float4 z = make_float4(0.f, 0.f, 0.f, 0.f);
#pragma unroll
        for (int k = 0; k < 20; k++) dst[k * 256 + tid] = z;
        __threadfence();
        __syncthreads();
        if (tid == 0) atomicAdd(&g_zero_done, 1);
        return;
    }

    // ================= tail batch blocks =================
    if (blockIdx.x >= LB + ZB && blockIdx.x < LB + ZB + TB) {
        const int bi = blockIdx.x - (LB + ZB);
        if (tid == 0) { while (((volatile int*)&g_flag)[0] == 0) __nanosleep(200); }
        __syncthreads();
        __threadfence();
        for (int s = bi; s < NE * CAP; s += TB) {
            int n = g_slot_token[s];
            float4* dst = (float4*)(out_b + (size_t)s * DIM);
            if (n >= 0) {
                const float4* src = (const float4*)(x + (size_t)n * DIM);
                dst[tid] = src[tid];
            } else {
                dst[tid] = make_float4(0.f, 0.f, 0.f, 0.f);
            }
        }
        return;
    }

    // ================= patch block (very last) =================
    if (blockIdx.x == GRID - 1) {
        if (tid == 0) {
            while (((volatile int*)&g_flag)[0] == 0) __nanosleep(200);
            while (((volatile int*)&g_zero_done)[0] < ZB) __nanosleep(200);
        }
        __syncthreads();
        __threadfence();
        for (int j = tid; j < 2 * N_TOK; j += 256) {
            int k = (j >= N_TOK) ? 1 : 0;
            int n = j - k * N_TOK;
            unsigned off = g_tok_off[k][n];
            if (off != 0xFFFFFFFFu) {
                size_t wi = (size_t)n * (NE * CAP) + off;
                out[wi] = g_tok_val[k][n];
                out[NEC + wi] = 1.0f;
            }
        }
        return;
    }

    // ================= logits blocks [0, 512) =================
    __shared__ float4 ws4[NE * (DIM / 4)];   // 32 KB
    {
        const float4* w4 = (const float4*)w;
        for (int i = tid; i < NE * (DIM / 4); i += 256) ws4[i] = w4[i];
        __syncthreads();

        int warp = tid >> 5, lane = tid & 31;
        int n = blockIdx.x * 8 + warp;
        const float4* xr = (const float4*)(x + (size_t)n * DIM);
        float acc[NE];
#pragma unroll
        for (int e = 0; e < NE; e++) acc[e] = 0.f;
#pragma unroll
        for (int ii = 0; ii < (DIM / 4) / 32; ii++) {
            int i = lane + ii * 32;
            float4 xv = xr[i];
#pragma unroll
            for (int e = 0; e < NE; e++) {
                float4 wv = ws4[e * (DIM / 4) + i];
                acc[e] = fmaf(xv.x, wv.x, acc[e]);
                acc[e] = fmaf(xv.y, wv.y, acc[e]);
                acc[e] = fmaf(xv.z, wv.z, acc[e]);
                acc[e] = fmaf(xv.w, wv.w, acc[e]);
            }
        }
#pragma unroll
        for (int e = 0; e < NE; e++) {
#pragma unroll
            for (int o = 16; o > 0; o >>= 1)
                acc[e] += __shfl_down_sync(0xffffffffu, acc[e], o);
        }
        if (lane == 0) {
            int i0 = 0; float v0 = acc[0];
#pragma unroll
            for (int e = 1; e < NE; e++) if (acc[e] > v0) { v0 = acc[e]; i0 = e; }
            int i1 = -1; float v1 = -INFINITY;
#pragma unroll
            for (int e = 0; e < NE; e++)
                if (e != i0 && acc[e] > v1) { v1 = acc[e]; i1 = e; }
            float t = expf(v1 - v0);
            float den = 1.f + t;
            g_top[0][n] = i0;  g_top[1][n] = i1;
            g_prob[0][n] = 1.f / den;  g_prob[1][n] = t / den;
#pragma unroll
            for (int e = 0; e < NE; e++) out_l[(size_t)n * NE + e] = acc[e];
        }
        __threadfence();
        __syncthreads();
        if (tid == 0) atomicAdd(&g_done, 1);
    }

    if (blockIdx.x != 0) return;

    // ================= scan phase (block 0 only) =================
    if (tid == 0) { while (((volatile int*)&g_done)[0] < LB) __nanosleep(200); }
    __syncthreads();
    __threadfence();

    // init slot map
    for (int i = tid; i < NE * CAP; i += 256) g_slot_token[i] = -1;

    const int IPT = (2 * N_TOK) / 256;   // 32 items per thread, k-major order
    int lane = tid & 31, warp = tid >> 5;
    int j0 = tid * IPT;

    int cnt[NE];
#pragma unroll
    for (int e = 0; e < NE; e++) cnt[e] = 0;
    for (int i = 0; i < IPT; i++) {
        int j = j0 + i;
        int k = (j >= N_TOK) ? 1 : 0;
        int n = j - k * N_TOK;
        cnt[g_top[k][n]]++;
    }

    int incl[NE];
#pragma unroll
    for (int e = 0; e < NE; e++) {
        int v = cnt[e];
#pragma unroll
        for (int o = 1; o < 32; o <<= 1) {
            int u = __shfl_up_sync(0xffffffffu, v, o);
            if (lane >= o) v += u;
        }
        incl[e] = v;
    }

    __shared__ int wtot[8][NE];
    __shared__ int wexc[8][NE];
    if (lane == 31) {
#pragma unroll
        for (int e = 0; e < NE; e++) wtot[warp][e] = incl[e];
    }
    __syncthreads();
    if (tid == 0) {
        int run[NE];
#pragma unroll
        for (int e = 0; e < NE; e++) run[e] = 0;
        for (int w2 = 0; w2 < 8; w2++)
#pragma unroll
            for (int e = 0; e < NE; e++) {
                wexc[w2][e] = run[e];
                run[e] += wtot[w2][e];
            }
    }
    __syncthreads();

    int base[NE];
#pragma unroll
    for (int e = 0; e < NE; e++) base[e] = wexc[warp][e] + incl[e] - cnt[e];

    for (int i = 0; i < IPT; i++) {
        int j = j0 + i;
        int k = (j >= N_TOK) ? 1 : 0;
        int n = j - k * N_TOK;
        int e = g_top[k][n];
        int r = base[e]++;
        float p = g_prob[k][n];
        unsigned off = 0xFFFFFFFFu;
        if (r < CAP && p > 0.f) {
            off = (unsigned)(e * CAP + r);
            g_slot_token[off] = n;
        }
        g_tok_off[k][n] = off;
        g_tok_val[k][n] = p;
    }

    __threadfence();
    __syncthreads();
    if (tid == 0) atomicExch(&g_flag, 1);
}

// ---------------------------------------------------------------------------
extern "C" void kernel_launch(void* const* d_in, const int* in_sizes, int n_in,
                              void* d_out, int out_size) {
    const float* x = (const float*)d_in[0];
    const float* w = (const float*)d_in[1];
    if (in_sizes[0] == NE * DIM && in_sizes[1] == N_TOK * DIM) {
        const float* tmp = x; x = w; w = tmp;
    }

    float* out   = (float*)d_out;          // [N,E,cap] weights, then [N,E,cap] mask
    float* out_b = out + 2 * NEC;          // [E,cap,D]
    float* out_l = out + 2 * NEC + ECD;    // [B,S,E]

    k_init<<<1, 1>>>();
    k_fused<<<GRID, 256>>>(x, w, out, out_b, out_l);
}

// round 6
// speedup vs baseline: 1.2860x; 1.2860x over previous
#include <cuda_runtime.h>

// Fixed shapes
#define N_TOK 4096          // B*S
#define DIM   1024
#define NE    8
#define CAP   1280
#define NEC   ((size_t)N_TOK * NE * CAP)   // 41,943,040 floats
#define ECD   ((size_t)NE * CAP * DIM)     // 10,485,760 floats

#define ROW_F4   ((NE * CAP) / 4)          // 2560 float4 per token row
#define BATCH_BLOCKS 2560                  // 10240 slots / 4 per block

// Scratch (no allocations allowed -> device globals)
__device__ int      g_top[2][N_TOK];
__device__ float    g_prob[2][N_TOK];
__device__ int      g_slot_token[NE * CAP];
__device__ unsigned g_tok_off[2][N_TOK];   // e*CAP+r within token's [E,cap] row; ~0u = none
__device__ float    g_tok_val[2][N_TOK];

// ---------------------------------------------------------------------------
// K1: router logits + top-2 + 2-way softmax. 2 tokens per warp (amortizes the
// shared w reads). 256 blocks x 256 threads -> 16 tokens/block.
// ---------------------------------------------------------------------------
__global__ void __launch_bounds__(256) k_logits(const float* __restrict__ x,
                                                const float* __restrict__ w,
                                                float* __restrict__ logits_out) {
    __shared__ float4 ws4[NE * (DIM / 4)];   // 32 KB
    const int tid = threadIdx.x;
    const float4* w4 = (const float4*)w;
    for (int i = tid; i < NE * (DIM / 4); i += 256) ws4[i] = w4[i];
    __syncthreads();

    const int warp = tid >> 5, lane = tid & 31;
    const int n0 = blockIdx.x * 16 + warp * 2;     // tokens n0, n0+1

    const float4* xr0 = (const float4*)(x + (size_t)n0 * DIM);
    const float4* xr1 = (const float4*)(x + (size_t)(n0 + 1) * DIM);

    float acc0[NE], acc1[NE];
#pragma unroll
    for (int e = 0; e < NE; e++) { acc0[e] = 0.f; acc1[e] = 0.f; }

#pragma unroll
    for (int ii = 0; ii < (DIM / 4) / 32; ii++) {  // 8 iterations
        int i = lane + ii * 32;
        float4 x0 = xr0[i];
        float4 x1 = xr1[i];
#pragma unroll
        for (int e = 0; e < NE; e++) {
            float4 wv = ws4[e * (DIM / 4) + i];
            acc0[e] = fmaf(x0.x, wv.x, acc0[e]);
            acc0[e] = fmaf(x0.y, wv.y, acc0[e]);
            acc0[e] = fmaf(x0.z, wv.z, acc0[e]);
            acc0[e] = fmaf(x0.w, wv.w, acc0[e]);
            acc1[e] = fmaf(x1.x, wv.x, acc1[e]);
            acc1[e] = fmaf(x1.y, wv.y, acc1[e]);
            acc1[e] = fmaf(x1.z, wv.z, acc1[e]);
            acc1[e] = fmaf(x1.w, wv.w, acc1[e]);
        }
    }
#pragma unroll
    for (int e = 0; e < NE; e++) {
#pragma unroll
        for (int o = 16; o > 0; o >>= 1) {
            acc0[e] += __shfl_down_sync(0xffffffffu, acc0[e], o);
            acc1[e] += __shfl_down_sync(0xffffffffu, acc1[e], o);
        }
    }

    if (lane == 0) {
#pragma unroll
        for (int t = 0; t < 2; t++) {
            int n = n0 + t;
            float a[NE];
#pragma unroll
            for (int e = 0; e < NE; e++) a[e] = t ? acc1[e] : acc0[e];
            int i0 = 0; float v0 = a[0];
#pragma unroll
            for (int e = 1; e < NE; e++) if (a[e] > v0) { v0 = a[e]; i0 = e; }
            int i1 = -1; float v1 = -INFINITY;
#pragma unroll
            for (int e = 0; e < NE; e++)
                if (e != i0 && a[e] > v1) { v1 = a[e]; i1 = e; }
            float tt  = expf(v1 - v0);      // <= 1
            float den = 1.f + tt;
            g_top[0][n]  = i0;
            g_top[1][n]  = i1;
            g_prob[0][n] = 1.f / den;
            g_prob[1][n] = tt / den;
#pragma unroll
            for (int e = 0; e < NE; e++) logits_out[(size_t)n * NE + e] = a[e];
        }
    }
}

// ---------------------------------------------------------------------------
// K2: ordered per-expert rank scan over the 2*N assignments (k-major order).
// Single block, 1024 threads x 8 items. Produces ONLY scratch: per-token
// patch offsets/values and the slot->token map. No output writes.
// ---------------------------------------------------------------------------
__global__ void __launch_bounds__(1024) k_scan() {
    const int IPT = (2 * N_TOK) / 1024;   // 8
    int tid  = threadIdx.x;
    int lane = tid & 31, warp = tid >> 5;

    for (int i = tid; i < NE * CAP; i += 1024) g_slot_token[i] = -1;
    __syncthreads();

    int cnt[NE];
#pragma unroll
    for (int e = 0; e < NE; e++) cnt[e] = 0;
    int ex[IPT];
    int j0 = tid * IPT;
#pragma unroll
    for (int i = 0; i < IPT; i++) {
        int j = j0 + i;
        int k = (j >= N_TOK) ? 1 : 0;
        int n = j - k * N_TOK;
        int e = g_top[k][n];
        ex[i] = e;
        cnt[e]++;
    }

    int incl[NE];
#pragma unroll
    for (int e = 0; e < NE; e++) {
        int v = cnt[e];
#pragma unroll
        for (int o = 1; o < 32; o <<= 1) {
            int u = __shfl_up_sync(0xffffffffu, v, o);
            if (lane >= o) v += u;
        }
        incl[e] = v;
    }

    __shared__ int wtot[32][NE];
    __shared__ int wbase[32][NE];
    if (lane == 31) {
#pragma unroll
        for (int e = 0; e < NE; e++) wtot[warp][e] = incl[e];
    }
    __syncthreads();
    if (warp == 0) {
#pragma unroll
        for (int e = 0; e < NE; e++) {
            int v = wtot[lane][e];
            int iv = v;
#pragma unroll
            for (int o = 1; o < 32; o <<= 1) {
                int u = __shfl_up_sync(0xffffffffu, iv, o);
                if (lane >= o) iv += u;
            }
            wbase[lane][e] = iv - v;
        }
    }
    __syncthreads();

    int base[NE];
#pragma unroll
    for (int e = 0; e < NE; e++) base[e] = wbase[warp][e] + incl[e] - cnt[e];

#pragma unroll
    for (int i = 0; i < IPT; i++) {
        int j = j0 + i;
        int k = (j >= N_TOK) ? 1 : 0;
        int n = j - k * N_TOK;
        int e = ex[i];
        int r = base[e]++;
        float p = g_prob[k][n];
        unsigned off = 0xFFFFFFFFu;
        if (r < CAP && p > 0.f) {
            off = (unsigned)(e * CAP + r);
            g_slot_token[off] = n;
        }
        g_tok_off[k][n] = off;
        g_tok_val[k][n] = p;
    }
}

// ---------------------------------------------------------------------------
// K3: one streaming pass, two independent block roles, no smem, no sync:
//   blocks [0, 4096):      zero + inline-patch one token's w-row and m-row
//   blocks [4096, 6656):   expert batches, 4 slots per block
// ---------------------------------------------------------------------------
__global__ void __launch_bounds__(256) k_fill(const float* __restrict__ x,
                                              float* __restrict__ out,
                                              float* __restrict__ out_b) {
    const int tid = threadIdx.x;

    if (blockIdx.x < N_TOK) {
        const int n = blockIdx.x;
        const unsigned off0 = g_tok_off[0][n], off1 = g_tok_off[1][n];
        const float    v0p  = g_tok_val[0][n], v1p  = g_tok_val[1][n];
        const unsigned f0 = off0 >> 2, c0 = off0 & 3;
        const unsigned f1 = off1 >> 2, c1 = off1 & 3;

        float4* dw = (float4*)out + (size_t)n * ROW_F4;
        float4* dm = (float4*)out + NEC / 4 + (size_t)n * ROW_F4;

#pragma unroll
        for (int k = 0; k < ROW_F4 / 256; k++) {   // 10 iterations
            unsigned f = k * 256 + tid;
            float4 zw = make_float4(0.f, 0.f, 0.f, 0.f);
            float4 zm = make_float4(0.f, 0.f, 0.f, 0.f);
            if (f == f0) {
                switch (c0) {
                    case 0: zw.x = v0p; zm.x = 1.f; break;
                    case 1: zw.y = v0p; zm.y = 1.f; break;
                    case 2: zw.z = v0p; zm.z = 1.f; break;
                    default: zw.w = v0p; zm.w = 1.f; break;
                }
            }
            if (f == f1) {
                switch (c1) {
                    case 0: zw.x = v1p; zm.x = 1.f; break;
                    case 1: zw.y = v1p; zm.y = 1.f; break;
                    case 2: zw.z = v1p; zm.z = 1.f; break;
                    default: zw.w = v1p; zm.w = 1.f; break;
                }
            }
            dw[f] = zw;
            dm[f] = zm;
        }
        return;
    }

    // ---- batch blocks ----
    const int bi = blockIdx.x - N_TOK;     // 0..2559
#pragma unroll
    for (int j = 0; j < 4; j++) {
        int s = bi * 4 + j;
        int n = g_slot_token[s];
        float4* dst = (float4*)(out_b + (size_t)s * DIM);
        if (n >= 0) {
            const float4* src = (const float4*)(x + (size_t)n * DIM);
            dst[tid] = src[tid];
        } else {
            dst[tid] = make_float4(0.f, 0.f, 0.f, 0.f);
        }
    }
}

// ---------------------------------------------------------------------------
extern "C" void kernel_launch(void* const* d_in, const int* in_sizes, int n_in,
                              void* d_out, int out_size) {
    const float* x = (const float*)d_in[0];
    const float* w = (const float*)d_in[1];
    if (in_sizes[0] == NE * DIM && in_sizes[1] == N_TOK * DIM) {
        const float* tmp = x; x = w; w = tmp;
    }

    float* out   = (float*)d_out;          // [N,E,cap] weights, then [N,E,cap] mask
    float* out_b = out + 2 * NEC;          // [E,cap,D]
    float* out_l = out + 2 * NEC + ECD;    // [B,S,E]

    k_logits<<<N_TOK / 16, 256>>>(x, w, out_l);
    k_scan<<<1, 1024>>>();
    k_fill<<<N_TOK + BATCH_BLOCKS, 256>>>(x, out, out_b);
}